// round 4
// baseline (speedup 1.0000x reference)
#include <cuda_runtime.h>
#include <math.h>

#define T_TOKENS 16384
#define HID      2048
#define NEXP     64
#define BT       128            // tokens per block
#define KC       16             // k-chunk
#define NSTAGES  (HID / KC)     // 128
#define AST      (BT + 1)       // A smem stride (129, odd -> conflict-free STS)
#define LS       (NEXP + 4)     // logits smem stride (68 -> float4 aligned rows)

#define OFF_MULT  0
#define OFF_GATES (T_TOKENS * 2)
#define OFF_SEL   (OFF_GATES + T_TOKENS * NEXP)
#define OFF_Z     (OFF_SEL + T_TOKENS * 2)

#define NBLOCKS   (T_TOKENS / BT)   // 128

__device__ float g_zpart[NBLOCKS];

__device__ __forceinline__ float gsum8(float v) {
    v += __shfl_xor_sync(0xffffffffu, v, 4, 8);
    v += __shfl_xor_sync(0xffffffffu, v, 2, 8);
    v += __shfl_xor_sync(0xffffffffu, v, 1, 8);
    return v;
}

__global__ __launch_bounds__(256, 1)
void router_kernel(const float* __restrict__ x, const float* __restrict__ w,
                   float* __restrict__ out)
{
    // Union: GEMM buffers (As+Bs = 6176 floats) alias the logits buffer (8704 floats)
    __shared__ __align__(16) float sm[BT * LS];
    float* As = sm;                 // [2][KC][AST]  = 2*16*129 = 4128 floats
    float* Bs = sm + 2 * KC * AST;  // [2][KC][NEXP] = 2*16*64  = 2048 floats
    __shared__ float Zs[BT];

    const int tid = threadIdx.x;
    const int blk = blockIdx.x;
    const int tx  = tid & 15;   // expert quad: experts tx*4 .. tx*4+3
    const int ty  = tid >> 4;   // token octet: tokens  ty*8 .. ty*8+7

    // global-load indices (float4 granularity; 4 float4 per row per stage)
    const int ar0 = tid >> 2;          // token row 0..63
    const int ar1 = 64 + (tid >> 2);   // token row 64..127
    const int akq = tid & 3;           // which float4 within the 16-wide k chunk
    const int br  = tid >> 2;          // expert row 0..63
    const int bkq = tid & 3;

    const float4* xg = (const float4*)(x + (size_t)blk * BT * HID);
    const float4* wg = (const float4*)w;
    const int RW = HID / 4;  // 512 float4 per row

    float acc[8][4];
#pragma unroll
    for (int i = 0; i < 8; i++)
#pragma unroll
        for (int j = 0; j < 4; j++) acc[i][j] = 0.f;

    // ---- preload stage 0 ----
    float4 an0 = xg[(size_t)ar0 * RW + akq];
    float4 an1 = xg[(size_t)ar1 * RW + akq];
    float4 bn  = wg[(size_t)br  * RW + bkq];
    {
        const float* p0 = (const float*)&an0;
        const float* p1 = (const float*)&an1;
        const float* pb = (const float*)&bn;
#pragma unroll
        for (int j = 0; j < 4; j++) {
            As[(akq * 4 + j) * AST + ar0] = p0[j];
            As[(akq * 4 + j) * AST + ar1] = p1[j];
            Bs[(bkq * 4 + j) * NEXP + br] = pb[j];
        }
    }
    __syncthreads();

#pragma unroll 1
    for (int s = 0; s < NSTAGES; s++) {
        const int buf  = s & 1;
        const int nbuf = buf ^ 1;
        const bool pf = (s + 1 < NSTAGES);
        if (pf) {
            const int f4 = (s + 1) * (KC / 4);
            an0 = xg[(size_t)ar0 * RW + f4 + akq];
            an1 = xg[(size_t)ar1 * RW + f4 + akq];
            bn  = wg[(size_t)br  * RW + f4 + bkq];
        }

        const float* Ab = As + buf * (KC * AST);
        const float* Bb = Bs + buf * (KC * NEXP);
#pragma unroll
        for (int k = 0; k < KC; k++) {
            float4 b4 = *(const float4*)&Bb[k * NEXP + tx * 4];
            float a[8];
#pragma unroll
            for (int i = 0; i < 8; i++) a[i] = Ab[k * AST + ty * 8 + i];
#pragma unroll
            for (int i = 0; i < 8; i++) {
                acc[i][0] += a[i] * b4.x;
                acc[i][1] += a[i] * b4.y;
                acc[i][2] += a[i] * b4.z;
                acc[i][3] += a[i] * b4.w;
            }
        }

        if (pf) {
            const float* p0 = (const float*)&an0;
            const float* p1 = (const float*)&an1;
            const float* pb = (const float*)&bn;
            float* Aw = As + nbuf * (KC * AST);
            float* Bw = Bs + nbuf * (KC * NEXP);
#pragma unroll
            for (int j = 0; j < 4; j++) {
                Aw[(akq * 4 + j) * AST + ar0] = p0[j];
                Aw[(akq * 4 + j) * AST + ar1] = p1[j];
                Bw[(bkq * 4 + j) * NEXP + br] = pb[j];
            }
        }
        __syncthreads();
    }

    // ---- stage logits into smem (aliases As/Bs; all compute reads done) ----
#pragma unroll
    for (int i = 0; i < 8; i++)
#pragma unroll
        for (int j = 0; j < 4; j++)
            sm[(ty * 8 + i) * LS + tx * 4 + j] = acc[i][j];
    __syncthreads();

    // ---- routing: 8-lane groups, 4 tokens each ----
    const int grp = tid >> 3;   // 0..31
    const int gl  = tid & 7;    // 0..7
    const unsigned FULL = 0xffffffffu;
    const float NEG_INF = __int_as_float(0xff800000);

    for (int tt = 0; tt < 4; tt++) {
        const int t  = grp * 4 + tt;          // 0..127
        const int tg = blk * BT + t;

        float l[8];
        {
            float4 p0 = *(const float4*)&sm[t * LS + gl * 8];
            float4 p1 = *(const float4*)&sm[t * LS + gl * 8 + 4];
            l[0] = p0.x; l[1] = p0.y; l[2] = p0.z; l[3] = p0.w;
            l[4] = p1.x; l[5] = p1.y; l[6] = p1.z; l[7] = p1.w;
        }

        // pass 1: max + first-index argmax
        float mx = l[0]; int ax = gl * 8;
#pragma unroll
        for (int i = 1; i < 8; i++)
            if (l[i] > mx) { mx = l[i]; ax = gl * 8 + i; }
#pragma unroll
        for (int m = 4; m; m >>= 1) {
            float ov = __shfl_xor_sync(FULL, mx, m, 8);
            int   oi = __shfl_xor_sync(FULL, ax, m, 8);
            if (ov > mx || (ov == mx && oi < ax)) { mx = ov; ax = oi; }
        }

        float e[8];
        float so = 0.f, s1 = 0.f;
#pragma unroll
        for (int i = 0; i < 8; i++) { e[i] = expf(l[i] - mx); so += e[i]; }
#pragma unroll
        for (int i = 0; i < 8; i++) {
            float f = fmaxf(fabsf(l[i]), mx);
            if (!((mx - l[i]) / f > 0.02f)) s1 += e[i];   // NaN-exact mask semantics
        }
        so = gsum8(so);
        s1 = gsum8(s1);

        // pass 2: mask out ax, recompute max/argmax
        float mx2; int ax2;
        {
            float l2_0 = (gl * 8 == ax) ? NEG_INF : l[0];
            mx2 = l2_0; ax2 = gl * 8;
#pragma unroll
            for (int i = 1; i < 8; i++) {
                float v = (gl * 8 + i == ax) ? NEG_INF : l[i];
                if (v > mx2) { mx2 = v; ax2 = gl * 8 + i; }
            }
#pragma unroll
            for (int m = 4; m; m >>= 1) {
                float ov = __shfl_xor_sync(FULL, mx2, m, 8);
                int   oi = __shfl_xor_sync(FULL, ax2, m, 8);
                if (ov > mx2 || (ov == mx2 && oi < ax2)) { mx2 = ov; ax2 = oi; }
            }
        }
        float s2 = 0.f;
#pragma unroll
        for (int i = 0; i < 8; i++) {
            int ei = gl * 8 + i;
            if (ei != ax) {
                float f = fmaxf(fabsf(l[i]), mx2);
                if (!((mx2 - l[i]) / f > 0.02f)) s2 += expf(l[i] - mx2);
            }
        }
        s2 = gsum8(s2);

        // writes
        const float inv = 1.f / so;
        float4 g0, g1;
        g0.x = e[0] * inv; g0.y = e[1] * inv; g0.z = e[2] * inv; g0.w = e[3] * inv;
        g1.x = e[4] * inv; g1.y = e[5] * inv; g1.z = e[6] * inv; g1.w = e[7] * inv;
        *(float4*)&out[OFF_GATES + (size_t)tg * NEXP + gl * 8]     = g0;
        *(float4*)&out[OFF_GATES + (size_t)tg * NEXP + gl * 8 + 4] = g1;

        if (gl == 0) {
            out[OFF_MULT + tg * 2 + 0] = 1.f / s1;
            out[OFF_MULT + tg * 2 + 1] = 1.f / s2;
            out[OFF_SEL  + tg * 2 + 0] = (float)ax;
            out[OFF_SEL  + tg * 2 + 1] = (float)ax2;
            float lse = mx + logf(so);
            Zs[t] = lse * lse;
        }
    }
    __syncthreads();

    // deterministic block z-reduction (warp 0, fixed order)
    if (tid < 32) {
        float v = ((Zs[tid] + Zs[tid + 32]) + Zs[tid + 64]) + Zs[tid + 96];
#pragma unroll
        for (int m = 16; m; m >>= 1) v += __shfl_xor_sync(0xffffffffu, v, m, 32);
        if (tid == 0) g_zpart[blk] = v;
    }
}

__global__ void zfinal_kernel(float* __restrict__ out)
{
    __shared__ float s[NBLOCKS];
    const int t = threadIdx.x;
    s[t] = g_zpart[t];
    __syncthreads();
#pragma unroll
    for (int st = NBLOCKS / 2; st > 0; st >>= 1) {
        if (t < st) s[t] += s[t + st];
        __syncthreads();
    }
    if (t == 0) out[OFF_Z] = 0.001f * s[0] / (float)T_TOKENS;
}

extern "C" void kernel_launch(void* const* d_in, const int* in_sizes, int n_in,
                              void* d_out, int out_size)
{
    const float* x = (const float*)d_in[0];
    const float* w = (const float*)d_in[1];
    float* out = (float*)d_out;
    router_kernel<<<NBLOCKS, 256>>>(x, w, out);
    zfinal_kernel<<<1, NBLOCKS>>>(out);
}

// round 5
// speedup vs baseline: 1.0600x; 1.0600x over previous
#include <cuda_runtime.h>
#include <math.h>

#define T_TOKENS 16384
#define HID      2048
#define NEXP     64
#define BT       128            // tokens per block
#define KC       16             // k-chunk
#define NSTAGES  (HID / KC)     // 128
#define AST      (BT + 4)       // A smem stride (132: 16B-aligned rows for LDS.128)
#define LS       (NEXP + 4)     // logits smem stride (68 -> float4 aligned rows)

#define OFF_MULT  0
#define OFF_GATES (T_TOKENS * 2)
#define OFF_SEL   (OFF_GATES + T_TOKENS * NEXP)
#define OFF_Z     (OFF_SEL + T_TOKENS * 2)

#define NBLOCKS   (T_TOKENS / BT)   // 128

__device__ float g_zpart[NBLOCKS];

__device__ __forceinline__ float gsum8(float v) {
    v += __shfl_xor_sync(0xffffffffu, v, 4, 8);
    v += __shfl_xor_sync(0xffffffffu, v, 2, 8);
    v += __shfl_xor_sync(0xffffffffu, v, 1, 8);
    return v;
}

// packed fp32x2 FMA: d = a*b + d  (per 32-bit lane, exact fp32 rounding)
__device__ __forceinline__ void ffma2(unsigned long long& d,
                                      unsigned long long a,
                                      unsigned long long b) {
    asm("fma.rn.f32x2 %0, %1, %2, %0;" : "+l"(d) : "l"(a), "l"(b));
}

__device__ __forceinline__ unsigned long long dup2(float v) {
    unsigned long long r; unsigned u = __float_as_uint(v);
    asm("mov.b64 %0, {%1, %2};" : "=l"(r) : "r"(u), "r"(u));
    return r;
}

__global__ __launch_bounds__(256, 1)
void router_kernel(const float* __restrict__ x, const float* __restrict__ w,
                   float* __restrict__ out)
{
    // Union: GEMM buffers (As+Bs = 6272 floats) alias the logits buffer (8704 floats)
    __shared__ __align__(16) float sm[BT * LS];
    float* As = sm;                 // [2][KC][AST]  = 2*16*132 = 4224 floats
    float* Bs = sm + 2 * KC * AST;  // [2][KC][NEXP] = 2*16*64  = 2048 floats
    __shared__ float Zs[BT];

    const int tid = threadIdx.x;
    const int blk = blockIdx.x;
    const int tx  = tid & 15;   // expert quad: experts tx*4 .. tx*4+3
    const int ty  = tid >> 4;   // token octet: tokens  ty*8 .. ty*8+7

    // global-load indices (float4 granularity; 4 float4 per row per stage)
    const int ar0 = tid >> 2;          // token row 0..63
    const int ar1 = 64 + (tid >> 2);   // token row 64..127
    const int akq = tid & 3;           // which float4 within the 16-wide k chunk
    const int br  = tid >> 2;          // expert row 0..63
    const int bkq = tid & 3;

    const float4* xg = (const float4*)(x + (size_t)blk * BT * HID);
    const float4* wg = (const float4*)w;
    const int RW = HID / 4;  // 512 float4 per row

    // acc[i4][j]: token pair (ty*8+2*i4, +1) x expert (tx*4+j), packed f32x2
    unsigned long long acc[4][4];
#pragma unroll
    for (int i = 0; i < 4; i++)
#pragma unroll
        for (int j = 0; j < 4; j++) acc[i][j] = 0ull;

    // ---- preload stage 0 ----
    float4 an0 = xg[(size_t)ar0 * RW + akq];
    float4 an1 = xg[(size_t)ar1 * RW + akq];
    float4 bn  = wg[(size_t)br  * RW + bkq];
    {
        const float* p0 = (const float*)&an0;
        const float* p1 = (const float*)&an1;
        const float* pb = (const float*)&bn;
#pragma unroll
        for (int j = 0; j < 4; j++) {
            As[(akq * 4 + j) * AST + ar0] = p0[j];
            As[(akq * 4 + j) * AST + ar1] = p1[j];
            Bs[(bkq * 4 + j) * NEXP + br] = pb[j];
        }
    }
    __syncthreads();

#pragma unroll 1
    for (int s = 0; s < NSTAGES; s++) {
        const int buf  = s & 1;
        const int nbuf = buf ^ 1;
        const bool pf = (s + 1 < NSTAGES);
        if (pf) {
            const int f4 = (s + 1) * (KC / 4);
            an0 = xg[(size_t)ar0 * RW + f4 + akq];
            an1 = xg[(size_t)ar1 * RW + f4 + akq];
            bn  = wg[(size_t)br  * RW + f4 + bkq];
        }

        const float* Ab = As + buf * (KC * AST);
        const float* Bb = Bs + buf * (KC * NEXP);
#pragma unroll
        for (int k = 0; k < KC; k++) {
            // a: 4 token-pairs (8 consecutive tokens) via 2x LDS.128
            ulonglong2 ap01 = *(const ulonglong2*)&Ab[k * AST + ty * 8];
            ulonglong2 ap23 = *(const ulonglong2*)&Ab[k * AST + ty * 8 + 4];
            // b: 4 experts via 1x LDS.128, duplicated into f32x2
            float4 b4 = *(const float4*)&Bb[k * NEXP + tx * 4];
            unsigned long long bd0 = dup2(b4.x);
            unsigned long long bd1 = dup2(b4.y);
            unsigned long long bd2 = dup2(b4.z);
            unsigned long long bd3 = dup2(b4.w);

            ffma2(acc[0][0], ap01.x, bd0); ffma2(acc[0][1], ap01.x, bd1);
            ffma2(acc[0][2], ap01.x, bd2); ffma2(acc[0][3], ap01.x, bd3);
            ffma2(acc[1][0], ap01.y, bd0); ffma2(acc[1][1], ap01.y, bd1);
            ffma2(acc[1][2], ap01.y, bd2); ffma2(acc[1][3], ap01.y, bd3);
            ffma2(acc[2][0], ap23.x, bd0); ffma2(acc[2][1], ap23.x, bd1);
            ffma2(acc[2][2], ap23.x, bd2); ffma2(acc[2][3], ap23.x, bd3);
            ffma2(acc[3][0], ap23.y, bd0); ffma2(acc[3][1], ap23.y, bd1);
            ffma2(acc[3][2], ap23.y, bd2); ffma2(acc[3][3], ap23.y, bd3);
        }

        if (pf) {
            const float* p0 = (const float*)&an0;
            const float* p1 = (const float*)&an1;
            const float* pb = (const float*)&bn;
            float* Aw = As + nbuf * (KC * AST);
            float* Bw = Bs + nbuf * (KC * NEXP);
#pragma unroll
            for (int j = 0; j < 4; j++) {
                Aw[(akq * 4 + j) * AST + ar0] = p0[j];
                Aw[(akq * 4 + j) * AST + ar1] = p1[j];
                Bw[(bkq * 4 + j) * NEXP + br] = pb[j];
            }
        }
        __syncthreads();
    }

    // ---- stage logits into smem (aliases As/Bs; all compute reads done) ----
#pragma unroll
    for (int i4 = 0; i4 < 4; i4++)
#pragma unroll
        for (int j = 0; j < 4; j++) {
            unsigned long long v = acc[i4][j];
            sm[(ty * 8 + 2 * i4)     * LS + tx * 4 + j] = __uint_as_float((unsigned)v);
            sm[(ty * 8 + 2 * i4 + 1) * LS + tx * 4 + j] = __uint_as_float((unsigned)(v >> 32));
        }
    __syncthreads();

    // ---- routing: 8-lane groups, 4 tokens each ----
    const int grp = tid >> 3;   // 0..31
    const int gl  = tid & 7;    // 0..7
    const unsigned FULL = 0xffffffffu;
    const float NEG_INF = __int_as_float(0xff800000);

    for (int tt = 0; tt < 4; tt++) {
        const int t  = grp * 4 + tt;          // 0..127
        const int tg = blk * BT + t;

        float l[8];
        {
            float4 p0 = *(const float4*)&sm[t * LS + gl * 8];
            float4 p1 = *(const float4*)&sm[t * LS + gl * 8 + 4];
            l[0] = p0.x; l[1] = p0.y; l[2] = p0.z; l[3] = p0.w;
            l[4] = p1.x; l[5] = p1.y; l[6] = p1.z; l[7] = p1.w;
        }

        // pass 1: max + first-index argmax
        float mx = l[0]; int ax = gl * 8;
#pragma unroll
        for (int i = 1; i < 8; i++)
            if (l[i] > mx) { mx = l[i]; ax = gl * 8 + i; }
#pragma unroll
        for (int m = 4; m; m >>= 1) {
            float ov = __shfl_xor_sync(FULL, mx, m, 8);
            int   oi = __shfl_xor_sync(FULL, ax, m, 8);
            if (ov > mx || (ov == mx && oi < ax)) { mx = ov; ax = oi; }
        }

        float e[8];
        float so = 0.f, s1 = 0.f;
#pragma unroll
        for (int i = 0; i < 8; i++) { e[i] = expf(l[i] - mx); so += e[i]; }
#pragma unroll
        for (int i = 0; i < 8; i++) {
            float f = fmaxf(fabsf(l[i]), mx);
            if (!((mx - l[i]) / f > 0.02f)) s1 += e[i];   // NaN-exact mask semantics
        }
        so = gsum8(so);
        s1 = gsum8(s1);

        // pass 2: mask out ax, recompute max/argmax
        float mx2; int ax2;
        {
            float l2_0 = (gl * 8 == ax) ? NEG_INF : l[0];
            mx2 = l2_0; ax2 = gl * 8;
#pragma unroll
            for (int i = 1; i < 8; i++) {
                float v = (gl * 8 + i == ax) ? NEG_INF : l[i];
                if (v > mx2) { mx2 = v; ax2 = gl * 8 + i; }
            }
#pragma unroll
            for (int m = 4; m; m >>= 1) {
                float ov = __shfl_xor_sync(FULL, mx2, m, 8);
                int   oi = __shfl_xor_sync(FULL, ax2, m, 8);
                if (ov > mx2 || (ov == mx2 && oi < ax2)) { mx2 = ov; ax2 = oi; }
            }
        }
        float s2 = 0.f;
#pragma unroll
        for (int i = 0; i < 8; i++) {
            int ei = gl * 8 + i;
            if (ei != ax) {
                float f = fmaxf(fabsf(l[i]), mx2);
                if (!((mx2 - l[i]) / f > 0.02f)) s2 += expf(l[i] - mx2);
            }
        }
        s2 = gsum8(s2);

        // writes
        const float inv = 1.f / so;
        float4 g0, g1;
        g0.x = e[0] * inv; g0.y = e[1] * inv; g0.z = e[2] * inv; g0.w = e[3] * inv;
        g1.x = e[4] * inv; g1.y = e[5] * inv; g1.z = e[6] * inv; g1.w = e[7] * inv;
        *(float4*)&out[OFF_GATES + (size_t)tg * NEXP + gl * 8]     = g0;
        *(float4*)&out[OFF_GATES + (size_t)tg * NEXP + gl * 8 + 4] = g1;

        if (gl == 0) {
            out[OFF_MULT + tg * 2 + 0] = 1.f / s1;
            out[OFF_MULT + tg * 2 + 1] = 1.f / s2;
            out[OFF_SEL  + tg * 2 + 0] = (float)ax;
            out[OFF_SEL  + tg * 2 + 1] = (float)ax2;
            float lse = mx + logf(so);
            Zs[t] = lse * lse;
        }
    }
    __syncthreads();

    // deterministic block z-reduction (warp 0, fixed order)
    if (tid < 32) {
        float v = ((Zs[tid] + Zs[tid + 32]) + Zs[tid + 64]) + Zs[tid + 96];
#pragma unroll
        for (int m = 16; m; m >>= 1) v += __shfl_xor_sync(0xffffffffu, v, m, 32);
        if (tid == 0) g_zpart[blk] = v;
    }
}

__global__ void zfinal_kernel(float* __restrict__ out)
{
    __shared__ float s[NBLOCKS];
    const int t = threadIdx.x;
    s[t] = g_zpart[t];
    __syncthreads();
#pragma unroll
    for (int st = NBLOCKS / 2; st > 0; st >>= 1) {
        if (t < st) s[t] += s[t + st];
        __syncthreads();
    }
    if (t == 0) out[OFF_Z] = 0.001f * s[0] / (float)T_TOKENS;
}

extern "C" void kernel_launch(void* const* d_in, const int* in_sizes, int n_in,
                              void* d_out, int out_size)
{
    const float* x = (const float*)d_in[0];
    const float* w = (const float*)d_in[1];
    float* out = (float*)d_out;
    router_kernel<<<NBLOCKS, 256>>>(x, w, out);
    zfinal_kernel<<<1, NBLOCKS>>>(out);
}